// round 8
// baseline (speedup 1.0000x reference)
#include <cuda_runtime.h>
#include <math.h>

#define BS    8192
#define SL    49
#define CTXN  48
#define FD    11
#define GE    8
#define GA    16
#define GD    16
#define KS    68   /* padded row stride for K tile (bank-conflict-free score loop) */

// ---------------- scratch (static device globals; no runtime allocation) ----------------
__device__ double g_stats[18];
__device__ float  g_bns[9];
__device__ float  g_bnsh[9];
__device__ float  g_xe[(size_t)BS*SL*64];   // x_embed
__device__ float  g_ye[(size_t)BS*SL*64];   // y_embed (row 48 = learnable_y)
__device__ float  g_cs[(size_t)BS*SL*8];    // per token: cos(a0..a3), sin(a0..a3)
__device__ float  g_enc[(size_t)BS*138];    // [0:64) s0, [64:128) s1, [128:138) central_x

// ---------------- BN statistics ----------------
__global__ void k_zero(){ if (threadIdx.x < 18) g_stats[threadIdx.x] = 0.0; }

__global__ __launch_bounds__(256) void k_stats(const float* __restrict__ in){
  float s[9], q[9];
  #pragma unroll
  for (int c=0;c<9;c++){ s[c]=0.f; q[c]=0.f; }
  int stride = gridDim.x*blockDim.x;
  for (int r = blockIdx.x*blockDim.x + threadIdx.x; r < BS*SL; r += stride){
    const float* row = in + (size_t)r*FD;
    #pragma unroll
    for (int c=0;c<8;c++){ float v=row[c]; s[c]+=v; q[c]+=v*v; }
    { float v=row[10]; s[8]+=v; q[8]+=v*v; }
  }
  #pragma unroll
  for (int c=0;c<9;c++){
    #pragma unroll
    for (int o=16;o>0;o>>=1){
      s[c] += __shfl_down_sync(0xFFFFFFFFu, s[c], o);
      q[c] += __shfl_down_sync(0xFFFFFFFFu, q[c], o);
    }
  }
  if ((threadIdx.x & 31)==0){
    #pragma unroll
    for (int c=0;c<9;c++){
      atomicAdd(&g_stats[c],   (double)s[c]);
      atomicAdd(&g_stats[9+c], (double)q[c]);
    }
  }
}

__global__ void k_bnfin(const float* __restrict__ gam, const float* __restrict__ bet){
  int c = threadIdx.x;
  if (c < 9){
    double N = (double)BS*(double)SL;
    double mean = g_stats[c]/N;
    double var  = g_stats[9+c]/N - mean*mean;
    float sc = (float)((double)gam[c]/sqrt(var + 1e-5));
    g_bns[c]  = sc;
    g_bnsh[c] = bet[c] - (float)mean*sc;
  }
}

// ---------------- embeddings + rope table + central_x ----------------
#define EMB_SMEM_F (512+64+4096+64+64+64+4096+64+64+9+9+588+3136)
__global__ __launch_bounds__(256) void k_embed(
    const float* __restrict__ in,
    const float* __restrict__ xw1, const float* __restrict__ xb1,
    const float* __restrict__ xw2, const float* __restrict__ xb2,
    const float* __restrict__ yw1, const float* __restrict__ yb1,
    const float* __restrict__ yw2, const float* __restrict__ yb2,
    const float* __restrict__ ly)
{
  extern __shared__ float sm[];
  float* s_xw1 = sm;            // 8x64
  float* s_xb1 = s_xw1+512;
  float* s_xw2 = s_xb1+64;      // 64x64
  float* s_xb2 = s_xw2+4096;
  float* s_yw1 = s_xb2+64;      // 1x64
  float* s_yb1 = s_yw1+64;
  float* s_yw2 = s_yb1+64;      // 64x64
  float* s_yb2 = s_yw2+4096;
  float* s_ly  = s_yb2+64;
  float* s_bns = s_ly+64;
  float* s_bnsh= s_bns+9;
  float* s_f   = s_bnsh+9;      // [49][12]
  float* s_h   = s_f+588;       // [49][64]
  int tid = threadIdx.x;

  for (int u=tid; u<512; u+=256) s_xw1[u]=xw1[u];
  for (int u=tid; u<4096; u+=256){ s_xw2[u]=xw2[u]; s_yw2[u]=yw2[u]; }
  if (tid<64){
    s_xb1[tid]=xb1[tid]; s_xb2[tid]=xb2[tid];
    s_yw1[tid]=yw1[tid]; s_yb1[tid]=yb1[tid]; s_yb2[tid]=yb2[tid];
    s_ly[tid]=ly[tid];
  }
  if (tid<9){ s_bns[tid]=g_bns[tid]; s_bnsh[tid]=g_bnsh[tid]; }
  __syncthreads();

  for (int e=0; e<GE; e++){
    int b = blockIdx.x*GE + e;
    const float* rowb = in + (size_t)b*SL*FD;
    // load + batchnorm (cols 0..7 -> stats 0..7, col 10 -> stat 8; cols 8,9 raw)
    for (int u=tid; u<SL*FD; u+=256){
      int t = u/FD, c = u - t*FD;
      float v = rowb[u];
      if (c < 8)        v = v*s_bns[c] + s_bnsh[c];
      else if (c == 10) v = v*s_bns[8] + s_bnsh[8];
      s_f[t*12+c] = v;
    }
    __syncthreads();
    // rope cos/sin table + central_x
    if (tid < SL){
      int t = tid;
      float x = s_f[t*12+8], y = s_f[t*12+9];
      float a[4] = {x*10.f, y*10.f, x, y};
      float* cp = g_cs + ((size_t)b*SL + t)*8;
      #pragma unroll
      for (int p=0;p<4;p++){ float ss, cc; sincosf(a[p], &ss, &cc); cp[p]=cc; cp[4+p]=ss; }
    } else if (tid>=64 && tid<74){
      int c = tid-64;
      g_enc[(size_t)b*138 + 128 + c] = s_f[48*12+c];
    }
    // x hidden: tanhshrink(f[:, :8] @ w1 + b1), all 49 tokens
    for (int u=tid; u<SL*64; u+=256){
      int t = u>>6, j = u&63;
      float acc = s_xb1[j];
      #pragma unroll
      for (int i=0;i<8;i++) acc += s_f[t*12+i]*s_xw1[i*64+j];
      s_h[u] = acc - tanhf(acc);
    }
    __syncthreads();
    // x out: h @ w2 + b2  (12-row register tile + row 48)
    {
      int j = tid&63, tb = tid>>6;
      float acc[12];
      #pragma unroll
      for (int m=0;m<12;m++) acc[m] = s_xb2[j];
      for (int k=0;k<64;k++){
        float w = s_xw2[k*64+j];
        #pragma unroll
        for (int m=0;m<12;m++) acc[m] += s_h[(tb+4*m)*64+k]*w;
      }
      float* op = g_xe + (size_t)b*SL*64;
      #pragma unroll
      for (int m=0;m<12;m++) op[(tb+4*m)*64+j] = acc[m];
      if (tid < 64){
        float a48 = s_xb2[tid];
        for (int k=0;k<64;k++) a48 += s_h[48*64+k]*s_xw2[k*64+tid];
        op[48*64+tid] = a48;
      }
    }
    __syncthreads();
    // y hidden (tokens 0..47)
    for (int u=tid; u<CTXN*64; u+=256){
      int t = u>>6, j = u&63;
      float acc = s_f[t*12+10]*s_yw1[j] + s_yb1[j];
      s_h[u] = acc - tanhf(acc);
    }
    __syncthreads();
    // y out + learnable_y at row 48
    {
      int j = tid&63, tb = tid>>6;
      float acc[12];
      #pragma unroll
      for (int m=0;m<12;m++) acc[m] = s_yb2[j];
      for (int k=0;k<64;k++){
        float w = s_yw2[k*64+j];
        #pragma unroll
        for (int m=0;m<12;m++) acc[m] += s_h[(tb+4*m)*64+k]*w;
      }
      float* op = g_ye + (size_t)b*SL*64;
      #pragma unroll
      for (int m=0;m<12;m++) op[(tb+4*m)*64+j] = acc[m];
      if (tid<64) op[48*64+tid] = s_ly[tid];
    }
    __syncthreads();
  }
}

// ---------------- attention (2 self-attn layers + cross-attn), per stream ----------------
#define ATTN_SMEM_F (16384 + GA*256 + 3072 + 48*KS + 3072 + 384 + 48 + 256 + 256 + 32*50 + 64+64+8+256+256+32+64)
__global__ __launch_bounds__(256) void k_attn(
  const float* __restrict__ dists, const float* __restrict__ hidden,
  const float* __restrict__ Wq,  const float* __restrict__ Wk,
  const float* __restrict__ Wv,  const float* __restrict__ Wo,
  const float* __restrict__ Wq2, const float* __restrict__ Wk2,
  const float* __restrict__ Wv2, const float* __restrict__ Wo2)
{
  extern __shared__ float sm[];
  float* sW  = sm;                 // [4][64][64]  q,k,v,o
  float* sH  = sW + 16384;         // [GA][4][64]
  float* sCtx= sH + GA*256;        // [48][64]
  float* sK  = sCtx + 3072;        // [48][KS]
  float* sV  = sK + 48*KS;         // [48][64]
  float* sCS = sV + 3072;          // [48][8]
  float* sD  = sCS + 384;          // [48]
  float* sQ  = sD + 48;            // [4][64]
  float* sA  = sQ + 256;           // [4][64]
  float* sSc = sA + 256;           // [32][50]
  float* sqv = sSc + 32*50;        // 64
  float* sqr = sqv + 64;           // 64
  float* scq = sqr + 64;           // 8
  float* sk2 = scq + 8;            // [4][64]
  float* sv2 = sk2 + 256;          // [4][64]
  float* sa2 = sv2 + 256;          // [8][4]
  float* so2 = sa2 + 32;           // 64

  int tid = threadIdx.x;
  int s   = blockIdx.y;
  const float* ctxsrc = (s==0) ? g_xe : g_ye;
  const float SCALE = 0.35355339059327373f;  // 1/sqrt(8)

  for (int u=tid; u<GA*256; u+=256) sH[u] = hidden[u & 255];

  for (int l=0; l<2; l++){
    __syncthreads();
    int off = (l*2+s)*4096;
    for (int u=tid; u<4096; u+=256){
      sW[u]       = Wq[off+u];
      sW[4096+u]  = Wk[off+u];
      sW[8192+u]  = Wv[off+u];
      sW[12288+u] = Wo[off+u];
    }
    __syncthreads();
    for (int e=0; e<GA; e++){
      int b = blockIdx.x*GA + e;
      const float* cp = ctxsrc + (size_t)b*SL*64;
      for (int u=tid; u<3072; u+=256) sCtx[u] = cp[u];
      for (int u=tid; u<384;  u+=256) sCS[u] = g_cs[(size_t)b*SL*8 + u];
      if (tid < 48) sD[tid] = dists[(size_t)b*SL + tid];
      __syncthreads();
      // q = H[e] @ Wq  (4x64 outputs)
      {
        int i = tid>>6, j = tid&63;
        float acc = 0.f;
        for (int k=0;k<64;k++) acc += sH[e*256 + i*64 + k]*sW[k*64+j];
        sQ[tid] = acc;
      }
      // K,V = ctx @ Wk / ctx @ Wv  (fused; 2-col x 6-row register tiles)
      {
        int jl = tid&31, tr = tid>>5;
        float ak[12], av[12];
        #pragma unroll
        for (int m=0;m<12;m++){ ak[m]=0.f; av[m]=0.f; }
        for (int k=0;k<64;k++){
          float wk0 = sW[4096 + k*64 + jl],  wk1 = sW[4096 + k*64 + jl + 32];
          float wv0 = sW[8192 + k*64 + jl],  wv1 = sW[8192 + k*64 + jl + 32];
          #pragma unroll
          for (int m=0;m<6;m++){
            float c = sCtx[(tr+8*m)*64 + k];
            ak[2*m]   += c*wk0; ak[2*m+1] += c*wk1;
            av[2*m]   += c*wv0; av[2*m+1] += c*wv1;
          }
        }
        #pragma unroll
        for (int m=0;m<6;m++){
          int t = tr + 8*m;
          sK[t*KS+jl] = ak[2*m]; sK[t*KS+jl+32] = ak[2*m+1];
          sV[t*64+jl] = av[2*m]; sV[t*64+jl+32] = av[2*m+1];
        }
      }
      __syncthreads();
      // rope on K (pairs within each head's 8 dims; angle index = pair & 3)
      for (int u=tid; u<1536; u+=256){
        int t = u>>5, p5 = u&31;
        int p = p5 & 3;
        float c = sCS[t*8+p], sn = sCS[t*8+4+p];
        float e0 = sK[t*KS+2*p5], e1 = sK[t*KS+2*p5+1];
        sK[t*KS+2*p5]   = c*e0 - sn*e1;
        sK[t*KS+2*p5+1] = sn*e0 + c*e1;
      }
      __syncthreads();
      // scores + softmax: 32 (head,query) groups of 8 lanes, 6 keys/lane
      {
        int g = tid>>3, l8 = tid&7;
        int h = g>>2, i = g&3;
        float sc[6];
        #pragma unroll
        for (int m=0;m<6;m++){
          int k = l8 + 8*m;
          float acc = 0.f;
          #pragma unroll
          for (int d=0;d<8;d++) acc += sQ[i*64+h*8+d]*sK[k*KS+h*8+d];
          sc[m] = acc*SCALE - sD[k];
        }
        float mx = sc[0];
        #pragma unroll
        for (int m=1;m<6;m++) mx = fmaxf(mx, sc[m]);
        #pragma unroll
        for (int o=4;o>0;o>>=1) mx = fmaxf(mx, __shfl_xor_sync(0xFFFFFFFFu, mx, o, 8));
        float sum = 0.f;
        #pragma unroll
        for (int m=0;m<6;m++){ sc[m] = __expf(sc[m]-mx); sum += sc[m]; }
        #pragma unroll
        for (int o=4;o>0;o>>=1) sum += __shfl_xor_sync(0xFFFFFFFFu, sum, o, 8);
        float inv = 1.f/sum;
        #pragma unroll
        for (int m=0;m<6;m++) sSc[g*50 + l8 + 8*m] = sc[m]*inv;
      }
      __syncthreads();
      // attn out = a @ V  (4x64)
      {
        int i = tid>>6, j = tid&63, h = j>>3;
        const float* arow = sSc + (h*4+i)*50;
        float acc = 0.f;
        for (int k=0;k<48;k++) acc += arow[k]*sV[k*64+j];
        sA[tid] = acc;
      }
      __syncthreads();
      // H += att @ Wo
      {
        int i = tid>>6, j = tid&63;
        float acc = 0.f;
        for (int k=0;k<64;k++) acc += sA[i*64+k]*sW[12288+k*64+j];
        sH[e*256 + tid] += acc;
      }
      __syncthreads();
    }
  }
  // -------- cross-attention epilogue --------
  {
    int off2 = s*4096;
    for (int u=tid; u<4096; u+=256){
      sW[u]       = Wq2[off2+u];
      sW[4096+u]  = Wk2[off2+u];
      sW[8192+u]  = Wv2[off2+u];
      sW[12288+u] = Wo2[off2+u];
    }
    __syncthreads();
    for (int e=0; e<GA; e++){
      int b = blockIdx.x*GA + e;
      if (tid < 64)                 sqv[tid]    = ctxsrc[(size_t)b*SL*64 + 48*64 + tid];
      else if (tid >= 64 && tid<72) scq[tid-64] = g_cs[((size_t)b*SL + 48)*8 + (tid-64)];
      __syncthreads();
      // q raw + k2, v2 projections
      {
        int i = tid>>6, j = tid&63;
        float acck = 0.f, accv = 0.f;
        for (int k=0;k<64;k++){
          float hk = sH[e*256 + i*64 + k];
          acck += hk*sW[4096 + k*64 + j];
          accv += hk*sW[8192 + k*64 + j];
        }
        sk2[tid] = acck; sv2[tid] = accv;
        if (tid < 64){
          float accq = 0.f;
          for (int k=0;k<64;k++) accq += sqv[k]*sW[k*64+tid];
          sqr[tid] = accq;
        }
      }
      __syncthreads();
      if (tid < 32){  // rope on q
        int p = tid & 3;
        float c = scq[p], sn = scq[4+p];
        float e0 = sqr[2*tid], e1 = sqr[2*tid+1];
        sqr[2*tid]   = c*e0 - sn*e1;
        sqr[2*tid+1] = sn*e0 + c*e1;
      }
      __syncthreads();
      if (tid < 8){   // per-head scores + softmax over 4 keys
        int h = tid;
        float sc4[4];
        float mx = -1e30f;
        #pragma unroll
        for (int i=0;i<4;i++){
          float acc = 0.f;
          #pragma unroll
          for (int d=0;d<8;d++) acc += sqr[h*8+d]*sk2[i*64+h*8+d];
          sc4[i] = acc*SCALE;
          mx = fmaxf(mx, sc4[i]);
        }
        float sum = 0.f;
        #pragma unroll
        for (int i=0;i<4;i++){ sc4[i] = __expf(sc4[i]-mx); sum += sc4[i]; }
        float inv = 1.f/sum;
        #pragma unroll
        for (int i=0;i<4;i++) sa2[h*4+i] = sc4[i]*inv;
      }
      __syncthreads();
      if (tid < 64){  // att = a @ v2 (merged 64)
        int h = tid>>3;
        float acc = 0.f;
        #pragma unroll
        for (int i=0;i<4;i++) acc += sa2[h*4+i]*sv2[i*64+tid];
        so2[tid] = acc;
      }
      __syncthreads();
      if (tid < 64){  // out = att @ Wo2 -> encoding
        float acc = 0.f;
        for (int k=0;k<64;k++) acc += so2[k]*sW[12288+k*64+tid];
        g_enc[(size_t)b*138 + s*64 + tid] = acc;
      }
      __syncthreads();
    }
  }
}

// ---------------- decoder ----------------
#define DEC_SMEM_F (GD*138 + GD*512 + GD*256)
__global__ __launch_bounds__(256) void k_dec(
    const float* __restrict__ w0, const float* __restrict__ b0,
    const float* __restrict__ w1, const float* __restrict__ b1,
    const float* __restrict__ w2, const float* __restrict__ b2,
    float* __restrict__ out)
{
  extern __shared__ float sm[];
  float* sEnc = sm;                 // [16][138]
  float* sH1  = sEnc + GD*138;      // [16][512]
  float* sH2  = sH1 + GD*512;       // [16][256]
  int tid = threadIdx.x;
  size_t bbase = (size_t)blockIdx.x * GD;

  for (int u=tid; u<GD*138; u+=256) sEnc[u] = g_enc[bbase*138 + u];
  __syncthreads();

  // layer 0: 138 -> 512, tanhshrink; two column passes of 256
  #pragma unroll
  for (int p=0; p<2; p++){
    int j = tid + 256*p;
    float acc[GD];
    float bj = __ldg(&b0[j]);
    #pragma unroll
    for (int m=0;m<GD;m++) acc[m] = bj;
    for (int k=0;k<138;k++){
      float w = __ldg(&w0[k*512 + j]);
      #pragma unroll
      for (int m=0;m<GD;m++) acc[m] += sEnc[m*138+k]*w;
    }
    #pragma unroll
    for (int m=0;m<GD;m++){ float a = acc[m]; sH1[m*512 + j] = a - tanhf(a); }
  }
  __syncthreads();

  // layer 1: 512 -> 256, tanhshrink
  {
    int j = tid;
    float acc[GD];
    float bj = __ldg(&b1[j]);
    #pragma unroll
    for (int m=0;m<GD;m++) acc[m] = bj;
    for (int k=0;k<512;k++){
      float w = __ldg(&w1[k*256 + j]);
      #pragma unroll
      for (int m=0;m<GD;m++) acc[m] += sH1[m*512+k]*w;
    }
    #pragma unroll
    for (int m=0;m<GD;m++){ float a = acc[m]; sH2[m*256 + j] = a - tanhf(a); }
  }
  __syncthreads();

  // layer 2: 256 -> 1
  if (tid < 128){
    int e = tid>>3, l8 = tid&7;
    float acc = 0.f;
    for (int m=0;m<32;m++){
      int k = l8 + 8*m;
      acc += sH2[e*256+k]*__ldg(&w2[k]);
    }
    #pragma unroll
    for (int o=4;o>0;o>>=1) acc += __shfl_xor_sync(0xFFFFFFFFu, acc, o, 8);
    if (l8 == 0) out[bbase + e] = acc + __ldg(&b2[0]);
  }
}

// ---------------- launcher ----------------
extern "C" void kernel_launch(void* const* d_in, const int* in_sizes, int n_in,
                              void* d_out, int out_size) {
  const float* input = (const float*)d_in[0];
  const float* dists = (const float*)d_in[1];
  // d_in[2] = target_position (unused)
  const float* bn_g  = (const float*)d_in[3];
  const float* bn_b  = (const float*)d_in[4];
  const float* xw1   = (const float*)d_in[5];
  const float* xb1   = (const float*)d_in[6];
  const float* xw2   = (const float*)d_in[7];
  const float* xb2   = (const float*)d_in[8];
  const float* yw1   = (const float*)d_in[9];
  const float* yb1   = (const float*)d_in[10];
  const float* yw2   = (const float*)d_in[11];
  const float* yb2   = (const float*)d_in[12];
  const float* ly    = (const float*)d_in[13];
  const float* hid   = (const float*)d_in[14];
  const float* Wq    = (const float*)d_in[15];
  const float* Wk    = (const float*)d_in[16];
  const float* Wv    = (const float*)d_in[17];
  const float* Wo    = (const float*)d_in[18];
  const float* Wq2   = (const float*)d_in[19];
  const float* Wk2   = (const float*)d_in[20];
  const float* Wv2   = (const float*)d_in[21];
  const float* Wo2   = (const float*)d_in[22];
  const float* dw0   = (const float*)d_in[23];
  const float* db0   = (const float*)d_in[24];
  const float* dw1   = (const float*)d_in[25];
  const float* db1   = (const float*)d_in[26];
  const float* dw2   = (const float*)d_in[27];
  const float* db2   = (const float*)d_in[28];
  float* out = (float*)d_out;

  cudaFuncSetAttribute(k_embed, cudaFuncAttributeMaxDynamicSharedMemorySize, EMB_SMEM_F*4);
  cudaFuncSetAttribute(k_attn,  cudaFuncAttributeMaxDynamicSharedMemorySize, ATTN_SMEM_F*4);
  cudaFuncSetAttribute(k_dec,   cudaFuncAttributeMaxDynamicSharedMemorySize, DEC_SMEM_F*4);

  k_zero<<<1, 32>>>();
  k_stats<<<256, 256>>>(input);
  k_bnfin<<<1, 32>>>(bn_g, bn_b);
  k_embed<<<BS/GE, 256, EMB_SMEM_F*4>>>(input, xw1, xb1, xw2, xb2,
                                        yw1, yb1, yw2, yb2, ly);
  dim3 ag(BS/GA, 2);
  k_attn<<<ag, 256, ATTN_SMEM_F*4>>>(dists, hid, Wq, Wk, Wv, Wo, Wq2, Wk2, Wv2, Wo2);
  k_dec<<<BS/GD, 256, DEC_SMEM_F*4>>>(dw0, db0, dw1, db1, dw2, db2, out);
}

// round 15
// speedup vs baseline: 1.0723x; 1.0723x over previous
#include <cuda_runtime.h>
#include <math.h>

#define BS    8192
#define SL    49
#define CTXN  48
#define FD    11
#define GE    8
#define GA    16
#define GD    16
#define KS    68   /* padded row stride for K tile (bank-conflict-free score loop) */

// ---------------- scratch (static device globals; no runtime allocation) ----------------
__device__ double g_stats[18];
__device__ float  g_bns[9];
__device__ float  g_bnsh[9];
__device__ float  g_xe[(size_t)BS*SL*64];   // x_embed
__device__ float  g_ye[(size_t)BS*SL*64];   // y_embed (row 48 = learnable_y)
__device__ float  g_cs[(size_t)BS*SL*8];    // per token: cos(a0..a3), sin(a0..a3)
__device__ float  g_enc[(size_t)BS*138];    // [0:64) s0, [64:128) s1, [128:138) central_x

// ---------------- BN statistics ----------------
__global__ void k_zero(){ if (threadIdx.x < 18) g_stats[threadIdx.x] = 0.0; }

__global__ __launch_bounds__(256) void k_stats(const float* __restrict__ in){
  float s[9], q[9];
  #pragma unroll
  for (int c=0;c<9;c++){ s[c]=0.f; q[c]=0.f; }
  int stride = gridDim.x*blockDim.x;
  for (int r = blockIdx.x*blockDim.x + threadIdx.x; r < BS*SL; r += stride){
    const float* row = in + (size_t)r*FD;
    #pragma unroll
    for (int c=0;c<8;c++){ float v=row[c]; s[c]+=v; q[c]+=v*v; }
    { float v=row[10]; s[8]+=v; q[8]+=v*v; }
  }
  #pragma unroll
  for (int c=0;c<9;c++){
    #pragma unroll
    for (int o=16;o>0;o>>=1){
      s[c] += __shfl_down_sync(0xFFFFFFFFu, s[c], o);
      q[c] += __shfl_down_sync(0xFFFFFFFFu, q[c], o);
    }
  }
  if ((threadIdx.x & 31)==0){
    #pragma unroll
    for (int c=0;c<9;c++){
      atomicAdd(&g_stats[c],   (double)s[c]);
      atomicAdd(&g_stats[9+c], (double)q[c]);
    }
  }
}

__global__ void k_bnfin(const float* __restrict__ gam, const float* __restrict__ bet){
  int c = threadIdx.x;
  if (c < 9){
    double N = (double)BS*(double)SL;
    double mean = g_stats[c]/N;
    double var  = g_stats[9+c]/N - mean*mean;
    float sc = (float)((double)gam[c]/sqrt(var + 1e-5));
    g_bns[c]  = sc;
    g_bnsh[c] = bet[c] - (float)mean*sc;
  }
}

// ---------------- embeddings + rope table + central_x ----------------
#define EMB_SMEM_F (512+64+4096+64+64+64+4096+64+64+9+9+588+3136)
__global__ __launch_bounds__(256) void k_embed(
    const float* __restrict__ in,
    const float* __restrict__ xw1, const float* __restrict__ xb1,
    const float* __restrict__ xw2, const float* __restrict__ xb2,
    const float* __restrict__ yw1, const float* __restrict__ yb1,
    const float* __restrict__ yw2, const float* __restrict__ yb2,
    const float* __restrict__ ly)
{
  extern __shared__ float sm[];
  float* s_xw1 = sm;            // 8x64
  float* s_xb1 = s_xw1+512;
  float* s_xw2 = s_xb1+64;      // 64x64
  float* s_xb2 = s_xw2+4096;
  float* s_yw1 = s_xb2+64;      // 1x64
  float* s_yb1 = s_yw1+64;
  float* s_yw2 = s_yb1+64;      // 64x64
  float* s_yb2 = s_yw2+4096;
  float* s_ly  = s_yb2+64;
  float* s_bns = s_ly+64;
  float* s_bnsh= s_bns+9;
  float* s_f   = s_bnsh+9;      // [49][12]
  float* s_h   = s_f+588;       // [49][64]
  int tid = threadIdx.x;

  for (int u=tid; u<512; u+=256) s_xw1[u]=xw1[u];
  for (int u=tid; u<4096; u+=256){ s_xw2[u]=xw2[u]; s_yw2[u]=yw2[u]; }
  if (tid<64){
    s_xb1[tid]=xb1[tid]; s_xb2[tid]=xb2[tid];
    s_yw1[tid]=yw1[tid]; s_yb1[tid]=yb1[tid]; s_yb2[tid]=yb2[tid];
    s_ly[tid]=ly[tid];
  }
  if (tid<9){ s_bns[tid]=g_bns[tid]; s_bnsh[tid]=g_bnsh[tid]; }
  __syncthreads();

  for (int e=0; e<GE; e++){
    int b = blockIdx.x*GE + e;
    const float* rowb = in + (size_t)b*SL*FD;
    // load + batchnorm (cols 0..7 -> stats 0..7, col 10 -> stat 8; cols 8,9 raw)
    for (int u=tid; u<SL*FD; u+=256){
      int t = u/FD, c = u - t*FD;
      float v = rowb[u];
      if (c < 8)        v = v*s_bns[c] + s_bnsh[c];
      else if (c == 10) v = v*s_bns[8] + s_bnsh[8];
      s_f[t*12+c] = v;
    }
    __syncthreads();
    // rope cos/sin table + central_x
    if (tid < SL){
      int t = tid;
      float x = s_f[t*12+8], y = s_f[t*12+9];
      float a[4] = {x*10.f, y*10.f, x, y};
      float* cp = g_cs + ((size_t)b*SL + t)*8;
      #pragma unroll
      for (int p=0;p<4;p++){ float ss, cc; sincosf(a[p], &ss, &cc); cp[p]=cc; cp[4+p]=ss; }
    } else if (tid>=64 && tid<74){
      int c = tid-64;
      g_enc[(size_t)b*138 + 128 + c] = s_f[48*12+c];
    }
    // x hidden: tanhshrink(f[:, :8] @ w1 + b1), all 49 tokens
    for (int u=tid; u<SL*64; u+=256){
      int t = u>>6, j = u&63;
      float acc = s_xb1[j];
      #pragma unroll
      for (int i=0;i<8;i++) acc += s_f[t*12+i]*s_xw1[i*64+j];
      s_h[u] = acc - tanhf(acc);
    }
    __syncthreads();
    // x out: h @ w2 + b2  (12-row register tile + row 48)
    {
      int j = tid&63, tb = tid>>6;
      float acc[12];
      #pragma unroll
      for (int m=0;m<12;m++) acc[m] = s_xb2[j];
      for (int k=0;k<64;k++){
        float w = s_xw2[k*64+j];
        #pragma unroll
        for (int m=0;m<12;m++) acc[m] += s_h[(tb+4*m)*64+k]*w;
      }
      float* op = g_xe + (size_t)b*SL*64;
      #pragma unroll
      for (int m=0;m<12;m++) op[(tb+4*m)*64+j] = acc[m];
      if (tid < 64){
        float a48 = s_xb2[tid];
        for (int k=0;k<64;k++) a48 += s_h[48*64+k]*s_xw2[k*64+tid];
        op[48*64+tid] = a48;
      }
    }
    __syncthreads();
    // y hidden (tokens 0..47)
    for (int u=tid; u<CTXN*64; u+=256){
      int t = u>>6, j = u&63;
      float acc = s_f[t*12+10]*s_yw1[j] + s_yb1[j];
      s_h[u] = acc - tanhf(acc);
    }
    __syncthreads();
    // y out + learnable_y at row 48
    {
      int j = tid&63, tb = tid>>6;
      float acc[12];
      #pragma unroll
      for (int m=0;m<12;m++) acc[m] = s_yb2[j];
      for (int k=0;k<64;k++){
        float w = s_yw2[k*64+j];
        #pragma unroll
        for (int m=0;m<12;m++) acc[m] += s_h[(tb+4*m)*64+k]*w;
      }
      float* op = g_ye + (size_t)b*SL*64;
      #pragma unroll
      for (int m=0;m<12;m++) op[(tb+4*m)*64+j] = acc[m];
      if (tid<64) op[48*64+tid] = s_ly[tid];
    }
    __syncthreads();
  }
}

// ---------------- attention (2 self-attn layers + cross-attn), per stream ----------------
// smem: Wk+Wv only (8192 floats) -> 97.6 KB total -> 2 CTAs/SM.
// Wq/Wo (and Wq2/Wo2) read via __ldg: 16 KB, L1-resident, coalesced 128B lines.
#define ATTN_SMEM_F (8192 + GA*256 + 3072 + 48*KS + 3072 + 384 + 48 + 256 + 256 + 32*50 + 64+64+8+256+256+32+64)
__global__ __launch_bounds__(256) void k_attn(
  const float* __restrict__ dists, const float* __restrict__ hidden,
  const float* __restrict__ Wq,  const float* __restrict__ Wk,
  const float* __restrict__ Wv,  const float* __restrict__ Wo,
  const float* __restrict__ Wq2, const float* __restrict__ Wk2,
  const float* __restrict__ Wv2, const float* __restrict__ Wo2)
{
  extern __shared__ float sm[];
  float* sW  = sm;                 // [2][64][64]  k,v
  float* sH  = sW + 8192;          // [GA][4][64]
  float* sCtx= sH + GA*256;        // [48][64]
  float* sK  = sCtx + 3072;        // [48][KS]
  float* sV  = sK + 48*KS;         // [48][64]
  float* sCS = sV + 3072;          // [48][8]
  float* sD  = sCS + 384;          // [48]
  float* sQ  = sD + 48;            // [4][64]
  float* sA  = sQ + 256;           // [4][64]
  float* sSc = sA + 256;           // [32][50]
  float* sqv = sSc + 32*50;        // 64
  float* sqr = sqv + 64;           // 64
  float* scq = sqr + 64;           // 8
  float* sk2 = scq + 8;            // [4][64]
  float* sv2 = sk2 + 256;          // [4][64]
  float* sa2 = sv2 + 256;          // [8][4]
  float* so2 = sa2 + 32;           // 64

  int tid = threadIdx.x;
  int s   = blockIdx.y;
  const float* ctxsrc = (s==0) ? g_xe : g_ye;
  const float SCALE = 0.35355339059327373f;  // 1/sqrt(8)

  for (int u=tid; u<GA*256; u+=256) sH[u] = hidden[u & 255];

  for (int l=0; l<2; l++){
    __syncthreads();
    int off = (l*2+s)*4096;
    for (int u=tid; u<4096; u+=256){
      sW[u]       = Wk[off+u];
      sW[4096+u]  = Wv[off+u];
    }
    __syncthreads();
    for (int e=0; e<GA; e++){
      int b = blockIdx.x*GA + e;
      const float* cp = ctxsrc + (size_t)b*SL*64;
      for (int u=tid; u<3072; u+=256) sCtx[u] = cp[u];
      for (int u=tid; u<384;  u+=256) sCS[u] = g_cs[(size_t)b*SL*8 + u];
      if (tid < 48) sD[tid] = dists[(size_t)b*SL + tid];
      __syncthreads();
      // q = H[e] @ Wq  (4x64 outputs; Wq from L1-resident global)
      {
        int i = tid>>6, j = tid&63;
        float acc = 0.f;
        #pragma unroll 8
        for (int k=0;k<64;k++) acc += sH[e*256 + i*64 + k]*__ldg(&Wq[off + k*64 + j]);
        sQ[tid] = acc;
      }
      // K,V = ctx @ Wk / ctx @ Wv  (fused; 2-col x 6-row register tiles)
      {
        int jl = tid&31, tr = tid>>5;
        float ak[12], av[12];
        #pragma unroll
        for (int m=0;m<12;m++){ ak[m]=0.f; av[m]=0.f; }
        for (int k=0;k<64;k++){
          float wk0 = sW[k*64 + jl],         wk1 = sW[k*64 + jl + 32];
          float wv0 = sW[4096 + k*64 + jl],  wv1 = sW[4096 + k*64 + jl + 32];
          #pragma unroll
          for (int m=0;m<6;m++){
            float c = sCtx[(tr+8*m)*64 + k];
            ak[2*m]   += c*wk0; ak[2*m+1] += c*wk1;
            av[2*m]   += c*wv0; av[2*m+1] += c*wv1;
          }
        }
        #pragma unroll
        for (int m=0;m<6;m++){
          int t = tr + 8*m;
          sK[t*KS+jl] = ak[2*m]; sK[t*KS+jl+32] = ak[2*m+1];
          sV[t*64+jl] = av[2*m]; sV[t*64+jl+32] = av[2*m+1];
        }
      }
      __syncthreads();
      // rope on K (pairs within each head's 8 dims; angle index = pair & 3)
      for (int u=tid; u<1536; u+=256){
        int t = u>>5, p5 = u&31;
        int p = p5 & 3;
        float c = sCS[t*8+p], sn = sCS[t*8+4+p];
        float e0 = sK[t*KS+2*p5], e1 = sK[t*KS+2*p5+1];
        sK[t*KS+2*p5]   = c*e0 - sn*e1;
        sK[t*KS+2*p5+1] = sn*e0 + c*e1;
      }
      __syncthreads();
      // scores + softmax: 32 (head,query) groups of 8 lanes, 6 keys/lane
      {
        int g = tid>>3, l8 = tid&7;
        int h = g>>2, i = g&3;
        float sc[6];
        #pragma unroll
        for (int m=0;m<6;m++){
          int k = l8 + 8*m;
          float acc = 0.f;
          #pragma unroll
          for (int d=0;d<8;d++) acc += sQ[i*64+h*8+d]*sK[k*KS+h*8+d];
          sc[m] = acc*SCALE - sD[k];
        }
        float mx = sc[0];
        #pragma unroll
        for (int m=1;m<6;m++) mx = fmaxf(mx, sc[m]);
        #pragma unroll
        for (int o=4;o>0;o>>=1) mx = fmaxf(mx, __shfl_xor_sync(0xFFFFFFFFu, mx, o, 8));
        float sum = 0.f;
        #pragma unroll
        for (int m=0;m<6;m++){ sc[m] = __expf(sc[m]-mx); sum += sc[m]; }
        #pragma unroll
        for (int o=4;o>0;o>>=1) sum += __shfl_xor_sync(0xFFFFFFFFu, sum, o, 8);
        float inv = 1.f/sum;
        #pragma unroll
        for (int m=0;m<6;m++) sSc[g*50 + l8 + 8*m] = sc[m]*inv;
      }
      __syncthreads();
      // attn out = a @ V  (4x64)
      {
        int i = tid>>6, j = tid&63, h = j>>3;
        const float* arow = sSc + (h*4+i)*50;
        float acc = 0.f;
        for (int k=0;k<48;k++) acc += arow[k]*sV[k*64+j];
        sA[tid] = acc;
      }
      __syncthreads();
      // H += att @ Wo  (Wo from L1-resident global)
      {
        int i = tid>>6, j = tid&63;
        float acc = 0.f;
        #pragma unroll 8
        for (int k=0;k<64;k++) acc += sA[i*64+k]*__ldg(&Wo[off + k*64 + j]);
        sH[e*256 + tid] += acc;
      }
      __syncthreads();
    }
  }
  // -------- cross-attention epilogue --------
  {
    int off2 = s*4096;
    for (int u=tid; u<4096; u+=256){
      sW[u]       = Wk2[off2+u];
      sW[4096+u]  = Wv2[off2+u];
    }
    __syncthreads();
    for (int e=0; e<GA; e++){
      int b = blockIdx.x*GA + e;
      if (tid < 64)                 sqv[tid]    = ctxsrc[(size_t)b*SL*64 + 48*64 + tid];
      else if (tid >= 64 && tid<72) scq[tid-64] = g_cs[((size_t)b*SL + 48)*8 + (tid-64)];
      __syncthreads();
      // q raw + k2, v2 projections
      {
        int i = tid>>6, j = tid&63;
        float acck = 0.f, accv = 0.f;
        for (int k=0;k<64;k++){
          float hk = sH[e*256 + i*64 + k];
          acck += hk*sW[k*64 + j];
          accv += hk*sW[4096 + k*64 + j];
        }
        sk2[tid] = acck; sv2[tid] = accv;
        if (tid < 64){
          float accq = 0.f;
          #pragma unroll 8
          for (int k=0;k<64;k++) accq += sqv[k]*__ldg(&Wq2[off2 + k*64 + tid]);
          sqr[tid] = accq;
        }
      }
      __syncthreads();
      if (tid < 32){  // rope on q
        int p = tid & 3;
        float c = scq[p], sn = scq[4+p];
        float e0 = sqr[2*tid], e1 = sqr[2*tid+1];
        sqr[2*tid]   = c*e0 - sn*e1;
        sqr[2*tid+1] = sn*e0 + c*e1;
      }
      __syncthreads();
      if (tid < 8){   // per-head scores + softmax over 4 keys
        int h = tid;
        float sc4[4];
        float mx = -1e30f;
        #pragma unroll
        for (int i=0;i<4;i++){
          float acc = 0.f;
          #pragma unroll
          for (int d=0;d<8;d++) acc += sqr[h*8+d]*sk2[i*64+h*8+d];
          sc4[i] = acc*SCALE;
          mx = fmaxf(mx, sc4[i]);
        }
        float sum = 0.f;
        #pragma unroll
        for (int i=0;i<4;i++){ sc4[i] = __expf(sc4[i]-mx); sum += sc4[i]; }
        float inv = 1.f/sum;
        #pragma unroll
        for (int i=0;i<4;i++) sa2[h*4+i] = sc4[i]*inv;
      }
      __syncthreads();
      if (tid < 64){  // att = a @ v2 (merged 64)
        int h = tid>>3;
        float acc = 0.f;
        #pragma unroll
        for (int i=0;i<4;i++) acc += sa2[h*4+i]*sv2[i*64+tid];
        so2[tid] = acc;
      }
      __syncthreads();
      if (tid < 64){  // out = att @ Wo2 -> encoding
        float acc = 0.f;
        #pragma unroll 8
        for (int k=0;k<64;k++) acc += so2[k]*__ldg(&Wo2[off2 + k*64 + tid]);
        g_enc[(size_t)b*138 + s*64 + tid] = acc;
      }
      __syncthreads();
    }
  }
}

// ---------------- decoder ----------------
#define DEC_SMEM_F (GD*138 + GD*512 + GD*256)
__global__ __launch_bounds__(256) void k_dec(
    const float* __restrict__ w0, const float* __restrict__ b0,
    const float* __restrict__ w1, const float* __restrict__ b1,
    const float* __restrict__ w2, const float* __restrict__ b2,
    float* __restrict__ out)
{
  extern __shared__ float sm[];
  float* sEnc = sm;                 // [16][138]
  float* sH1  = sEnc + GD*138;      // [16][512]
  float* sH2  = sH1 + GD*512;       // [16][256]
  int tid = threadIdx.x;
  size_t bbase = (size_t)blockIdx.x * GD;

  for (int u=tid; u<GD*138; u+=256) sEnc[u] = g_enc[bbase*138 + u];
  __syncthreads();

  // layer 0: 138 -> 512, tanhshrink; two column passes of 256
  #pragma unroll
  for (int p=0; p<2; p++){
    int j = tid + 256*p;
    float acc[GD];
    float bj = __ldg(&b0[j]);
    #pragma unroll
    for (int m=0;m<GD;m++) acc[m] = bj;
    for (int k=0;k<138;k++){
      float w = __ldg(&w0[k*512 + j]);
      #pragma unroll
      for (int m=0;m<GD;m++) acc[m] += sEnc[m*138+k]*w;
    }
    #pragma unroll
    for (int m=0;m<GD;m++){ float a = acc[m]; sH1[m*512 + j] = a - tanhf(a); }
  }
  __syncthreads();

  // layer 1: 512 -> 256, tanhshrink
  {
    int j = tid;
    float acc[GD];
    float bj = __ldg(&b1[j]);
    #pragma unroll
    for (int m=0;m<GD;m++) acc[m] = bj;
    for (int k=0;k<512;k++){
      float w = __ldg(&w1[k*256 + j]);
      #pragma unroll
      for (int m=0;m<GD;m++) acc[m] += sH1[m*512+k]*w;
    }
    #pragma unroll
    for (int m=0;m<GD;m++){ float a = acc[m]; sH2[m*256 + j] = a - tanhf(a); }
  }
  __syncthreads();

  // layer 2: 256 -> 1
  if (tid < 128){
    int e = tid>>3, l8 = tid&7;
    float acc = 0.f;
    for (int m=0;m<32;m++){
      int k = l8 + 8*m;
      acc += sH2[e*256+k]*__ldg(&w2[k]);
    }
    #pragma unroll
    for (int o=4;o>0;o>>=1) acc += __shfl_xor_sync(0xFFFFFFFFu, acc, o, 8);
    if (l8 == 0) out[bbase + e] = acc + __ldg(&b2[0]);
  }
}

// ---------------- launcher ----------------
extern "C" void kernel_launch(void* const* d_in, const int* in_sizes, int n_in,
                              void* d_out, int out_size) {
  const float* input = (const float*)d_in[0];
  const float* dists = (const float*)d_in[1];
  // d_in[2] = target_position (unused)
  const float* bn_g  = (const float*)d_in[3];
  const float* bn_b  = (const float*)d_in[4];
  const float* xw1   = (const float*)d_in[5];
  const float* xb1   = (const float*)d_in[6];
  const float* xw2   = (const float*)d_in[7];
  const float* xb2   = (const float*)d_in[8];
  const float* yw1   = (const float*)d_in[9];
  const float* yb1   = (const float*)d_in[10];
  const float* yw2   = (const float*)d_in[11];
  const float* yb2   = (const float*)d_in[12];
  const float* ly    = (const float*)d_in[13];
  const float* hid   = (const float*)d_in[14];
  const float* Wq    = (const float*)d_in[15];
  const float* Wk    = (const float*)d_in[16];
  const float* Wv    = (const float*)d_in[17];
  const float* Wo    = (const float*)d_in[18];
  const float* Wq2   = (const float*)d_in[19];
  const float* Wk2   = (const float*)d_in[20];
  const float* Wv2   = (const float*)d_in[21];
  const float* Wo2   = (const float*)d_in[22];
  const float* dw0   = (const float*)d_in[23];
  const float* db0   = (const float*)d_in[24];
  const float* dw1   = (const float*)d_in[25];
  const float* db1   = (const float*)d_in[26];
  const float* dw2   = (const float*)d_in[27];
  const float* db2   = (const float*)d_in[28];
  float* out = (float*)d_out;

  cudaFuncSetAttribute(k_embed, cudaFuncAttributeMaxDynamicSharedMemorySize, EMB_SMEM_F*4);
  cudaFuncSetAttribute(k_attn,  cudaFuncAttributeMaxDynamicSharedMemorySize, ATTN_SMEM_F*4);
  cudaFuncSetAttribute(k_dec,   cudaFuncAttributeMaxDynamicSharedMemorySize, DEC_SMEM_F*4);

  k_zero<<<1, 32>>>();
  k_stats<<<256, 256>>>(input);
  k_bnfin<<<1, 32>>>(bn_g, bn_b);
  k_embed<<<BS/GE, 256, EMB_SMEM_F*4>>>(input, xw1, xb1, xw2, xb2,
                                        yw1, yb1, yw2, yb2, ly);
  dim3 ag(BS/GA, 2);
  k_attn<<<ag, 256, ATTN_SMEM_F*4>>>(dists, hid, Wq, Wk, Wv, Wo, Wq2, Wk2, Wv2, Wo2);
  k_dec<<<BS/GD, 256, DEC_SMEM_F*4>>>(dw0, db0, dw1, db1, dw2, db2, out);
}